// round 16
// baseline (speedup 1.0000x reference)
#include <cuda_runtime.h>
#include <cuda_fp16.h>
#include <math.h>

#define Bz   32
#define Nn   1024
#define CIN  128
#define Ff   64
#define OUTD 10
#define MAXDEG 96
#define EPSf 1e-5f

typedef unsigned long long ull;

// ---------------- scratch (device globals; no allocation) ----------------
__device__ int     g_adj[Bz * Nn * MAXDEG]; // adjacency lists (compacted per layer)
__device__ int     g_deg[Bz * Nn];
__device__ float   g_x[Bz * Nn * Ff];       // gconv output (layers 0,1)
__device__ __half2 g_uwh[Bz * Nn * 32];     // fp16 D*m*u  (gathered by spmm)
__device__ float   g_ud[Bz * Nn * Ff];      // D*D*u  (diag term, fp32)
__device__ float   g_D[Bz * Nn];
__device__ float   g_mask[Bz * Nn];
__device__ float   g_sc[Bz * Nn];           // tanh(y)*new_mask
__device__ int     g_nnodes[Bz * 3];
__device__ float   g_y[Bz * Nn];
__device__ float   g_xmax[Bz * Ff];         // layer-2 global max (atomicMax target)

// ------ 1) fused: adjacency extraction + layer-0 GEMM + D + uw/ud --------
__global__ void layer0_fused(const float* __restrict__ x,
                             const float* __restrict__ A,
                             const float* __restrict__ mask,
                             const int*   __restrict__ nn,
                             const float* __restrict__ W) {
    __shared__ float2 Ws[CIN * 32];
    const float2* W2 = (const float2*)W;
    for (int i = threadIdx.x; i < CIN * 32; i += 256) Ws[i] = W2[i];
    if (blockIdx.x == 0 && threadIdx.x < Bz) g_nnodes[threadIdx.x] = nn[threadIdx.x];
    int wid = threadIdx.x >> 5, lane = threadIdx.x & 31;
    int row0 = blockIdx.x * 32 + wid * 4;
    float2 xa[4], xb[4];
    #pragma unroll
    for (int r = 0; r < 4; ++r) {
        const float2* xr = (const float2*)(x + (size_t)(row0 + r) * CIN);
        xa[r] = __ldcs(xr + lane);
        xb[r] = __ldcs(xr + lane + 32);
    }
    int   deg[4]; float mrow[4];
    #pragma unroll
    for (int r = 0; r < 4; ++r) {
        int row = row0 + r;
        const float4* Arow4 = (const float4*)(A + (size_t)row * Nn);
        int* adj = g_adj + (size_t)row * MAXDEG;
        int cnt = 0;
        #pragma unroll
        for (int half = 0; half < 2; ++half) {
            float4 va[4];
            #pragma unroll
            for (int it = 0; it < 4; ++it)                       // MLP=4, streaming
                va[it] = __ldcs(Arow4 + (half * 4 + it) * 32 + lane);
            #pragma unroll
            for (int it = 0; it < 4; ++it) {
                int jb = (half * 4 + it) * 128 + lane * 4;
                #pragma unroll
                for (int s = 0; s < 4; ++s) {
                    float vs = (s == 0) ? va[it].x : (s == 1) ? va[it].y
                             : (s == 2) ? va[it].z : va[it].w;
                    unsigned bal = __ballot_sync(0xffffffffu, vs != 0.0f);
                    if (vs != 0.0f) {
                        int pos = cnt + __popc(bal & ((1u << lane) - 1u));
                        if (pos < MAXDEG) adj[pos] = jb + s;
                    }
                    cnt += __popc(bal);
                }
            }
        }
        deg[r]  = min(cnt, MAXDEG);
        mrow[r] = mask[row];
        if (lane == 0) {
            g_deg[row]  = deg[r];
            g_mask[row] = mrow[r];
        }
    }
    __syncthreads();
    float acc[4][2] = {};
    #pragma unroll
    for (int k2 = 0; k2 < 32; ++k2) {
        float2 wv0 = Ws[(2 * k2)     * 32 + lane];
        float2 wv1 = Ws[(2 * k2 + 1) * 32 + lane];
        #pragma unroll
        for (int r = 0; r < 4; ++r) {
            float u = __shfl_sync(0xffffffffu, xa[r].x, k2);
            float v = __shfl_sync(0xffffffffu, xa[r].y, k2);
            acc[r][0] = fmaf(u, wv0.x, fmaf(v, wv1.x, acc[r][0]));
            acc[r][1] = fmaf(u, wv0.y, fmaf(v, wv1.y, acc[r][1]));
        }
    }
    #pragma unroll
    for (int k2 = 0; k2 < 32; ++k2) {
        float2 wv0 = Ws[(64 + 2 * k2) * 32 + lane];
        float2 wv1 = Ws[(65 + 2 * k2) * 32 + lane];
        #pragma unroll
        for (int r = 0; r < 4; ++r) {
            float u = __shfl_sync(0xffffffffu, xb[r].x, k2);
            float v = __shfl_sync(0xffffffffu, xb[r].y, k2);
            acc[r][0] = fmaf(u, wv0.x, fmaf(v, wv1.x, acc[r][0]));
            acc[r][1] = fmaf(u, wv0.y, fmaf(v, wv1.y, acc[r][1]));
        }
    }
    #pragma unroll
    for (int r = 0; r < 4; ++r) {
        int row = row0 + r;
        float rowsum = mrow[r] * (float)deg[r] + 1.0f;   // +1: identity in A_hat
        float D = 1.0f / sqrtf(rowsum + EPSf);
        if (lane == 0) g_D[row] = D;
        float Dm = D * mrow[r], DD = D * D;
        g_uwh[(size_t)row * 32 + lane] = __floats2half2_rn(Dm * acc[r][0], Dm * acc[r][1]);
        ((float2*)g_ud)[(size_t)row * 32 + lane] = make_float2(DD * acc[r][0], DD * acc[r][1]);
    }
}

// ------- 2) pure GEMM: u = sc*(X@W); scale by precomputed D ---------------
__global__ void gemm_fused(const float* __restrict__ W) {
    __shared__ float2 Ws[Ff * 32];
    const float2* W2 = (const float2*)W;
    for (int i = threadIdx.x; i < Ff * 32; i += 256) Ws[i] = W2[i];
    int wid = threadIdx.x >> 5, lane = threadIdx.x & 31;
    int row0 = blockIdx.x * 32 + wid * 4;
    float2 xa[4];
    float  Dp[4], mp[4], sp[4];               // epilogue operands hoisted
    #pragma unroll
    for (int r = 0; r < 4; ++r) {
        xa[r] = ((const float2*)g_x)[(size_t)(row0 + r) * 32 + lane];
        Dp[r] = g_D[row0 + r];
        mp[r] = g_mask[row0 + r];
        sp[r] = g_sc[row0 + r];
    }
    __syncthreads();
    float acc[4][2] = {};
    #pragma unroll
    for (int k2 = 0; k2 < 32; ++k2) {
        float2 wv0 = Ws[(2 * k2)     * 32 + lane];
        float2 wv1 = Ws[(2 * k2 + 1) * 32 + lane];
        #pragma unroll
        for (int r = 0; r < 4; ++r) {
            float u = __shfl_sync(0xffffffffu, xa[r].x, k2);
            float v = __shfl_sync(0xffffffffu, xa[r].y, k2);
            acc[r][0] = fmaf(u, wv0.x, fmaf(v, wv1.x, acc[r][0]));
            acc[r][1] = fmaf(u, wv0.y, fmaf(v, wv1.y, acc[r][1]));
        }
    }
    #pragma unroll
    for (int r = 0; r < 4; ++r) {
        int row = row0 + r;
        float a0 = acc[r][0] * sp[r], a1 = acc[r][1] * sp[r];
        float Dm = Dp[r] * mp[r], DD = Dp[r] * Dp[r];
        g_uwh[(size_t)row * 32 + lane] = __floats2half2_rn(Dm * a0, Dm * a1);
        ((float2*)g_ud)[(size_t)row * 32 + lane] = make_float2(DD * a0, DD * a1);
    }
}

// -------------- shared gather body: fp16 gathers, fp32 accumulate ---------
__device__ __forceinline__ float2 spmm_body(int node, int lane,
                                            const float* __restrict__ bias) {
    int base = node & ~(Nn - 1);
    float D = g_D[node];
    float2 ud = ((const float2*)g_ud)[(size_t)node * 32 + lane];
    float2 bv = ((const float2*)bias)[lane];
    float s0 = 0.f, s1 = 0.f;
    if (g_mask[node] > 0.f) {
        const int* adj = g_adj + (size_t)node * MAXDEG;
        int deg = g_deg[node];
        const __half2* uwb = g_uwh + (size_t)base * 32 + lane;
        int t = 0;
        for (; t + 4 <= deg; t += 4) {
            int4 jv = *(const int4*)(adj + t);
            __half2 v0 = uwb[jv.x * 32];
            __half2 v1 = uwb[jv.y * 32];
            __half2 v2 = uwb[jv.z * 32];
            __half2 v3 = uwb[jv.w * 32];
            __half2 h = __hadd2(__hadd2(v0, v1), __hadd2(v2, v3));
            float2 f = __half22float2(h);
            s0 += f.x; s1 += f.y;
        }
        for (; t < deg; ++t) {
            float2 f = __half22float2(uwb[adj[t] * 32]);
            s0 += f.x; s1 += f.y;
        }
    }
    float x0 = fmaxf(fmaf(D, s0, ud.x + bv.x), 0.f);
    float x1 = fmaxf(fmaf(D, s1, ud.y + bv.y), 0.f);
    return make_float2(x0, x1);
}

// -------- 3) layers 0/1: x = gconv, + fused pooling score -----------------
__global__ void spmm_relu(const float* __restrict__ bias,
                          const float* __restrict__ p) {
    int node = (blockIdx.x * blockDim.x + threadIdx.x) >> 5;
    int lane = threadIdx.x & 31;
    float2 xv = spmm_body(node, lane, bias);
    ((float2*)g_x)[(size_t)node * 32 + lane] = xv;
    float2 pv = ((const float2*)p)[lane];
    float d = xv.x * pv.x + xv.y * pv.y;
    float n = pv.x * pv.x + pv.y * pv.y;
    #pragma unroll
    for (int o = 16; o; o >>= 1) {
        d += __shfl_xor_sync(0xffffffffu, d, o);
        n += __shfl_xor_sync(0xffffffffu, n, o);
    }
    if (lane == 0) g_y[node] = d / sqrtf(n);
}

// -------- 3b) layer 2: gconv fused with global max (no g_x write) ---------
__global__ void spmm_max(const float* __restrict__ bias) {
    __shared__ float2 pm[8][32];
    int node = (blockIdx.x * blockDim.x + threadIdx.x) >> 5;
    int wid  = threadIdx.x >> 5;
    int lane = threadIdx.x & 31;
    float2 xv = spmm_body(node, lane, bias);
    pm[wid][lane] = xv;
    __syncthreads();
    if (wid == 0) {
        float2 mx = pm[0][lane];
        #pragma unroll
        for (int w = 1; w < 8; ++w) {
            float2 v = pm[w][lane];
            mx.x = fmaxf(mx.x, v.x);
            mx.y = fmaxf(mx.y, v.y);
        }
        int b = node >> 10;
        unsigned* gx = (unsigned*)g_xmax + b * Ff + 2 * lane;
        atomicMax(gx,     __float_as_uint(mx.x));   // x >= 0: bits monotone
        atomicMax(gx + 1, __float_as_uint(mx.y));
    }
}

// -- 4) pooling: bitonic sort + FUSED adjacency compaction + D -------------
__device__ __forceinline__ ull bsw(ull v, int i, int j, int k) {
    ull vp = __shfl_xor_sync(0xffffffffu, v, j);
    bool keepmin = ((i & j) == 0) == ((i & k) == 0);
    ull mn = v < vp ? v : vp;
    ull mx = v < vp ? vp : v;
    return keepmin ? mn : mx;
}

__global__ void pool_apply(int step) {
    __shared__ ull sk[Nn];
    __shared__ unsigned char rem[Nn];         // phase 1: removed; phase 2: active
    int b = blockIdx.x;
    int i = threadIdx.x;
    int node = b * Nn + i;
    float m = g_mask[node];
    float y = g_y[node];
    float ye = (m > 0.f) ? y : INFINITY;      // invalid nodes sort last
    unsigned int bits = __float_as_uint(ye);
    unsigned int mono = (bits & 0x80000000u) ? ~bits : (bits | 0x80000000u);
    ull v = ((ull)mono << 10) | (unsigned int)i;
    rem[i] = 0;
    if (step == 1 && i < Ff) g_xmax[b * Ff + i] = 0.f;   // reset for spmm_max
    int n  = g_nnodes[step * Bz + b];
    int nr = (int)((float)n * 0.2f);          // bit-matches f32 arithmetic
    if (i == 0) g_nnodes[(step + 1) * Bz + b] = n - nr;
    #pragma unroll
    for (int k = 2; k <= 32; k <<= 1)
        #pragma unroll
        for (int j = k >> 1; j > 0; j >>= 1) v = bsw(v, i, j, k);
    #pragma unroll 1
    for (int k = 64; k <= Nn; k <<= 1) {
        #pragma unroll 1
        for (int j = k >> 1; j >= 32; j >>= 1) {
            sk[i] = v;
            __syncthreads();
            ull vp = sk[i ^ j];
            bool keepmin = ((i & j) == 0) == ((i & k) == 0);
            v = keepmin ? (v < vp ? v : vp) : (v < vp ? vp : v);
            __syncthreads();
        }
        #pragma unroll
        for (int j = 16; j > 0; j >>= 1) v = bsw(v, i, j, k);
    }
    if (i < nr) rem[(int)(v & 1023u)] = 1;    // lowest-nr ranks removed
    __syncthreads();
    float newm = (m > 0.f && !rem[i]) ? 1.f : 0.f;
    g_mask[node] = newm;
    g_sc[node]   = tanhf(y) * newm;           // consumed by next gemm
    __syncthreads();
    rem[i] = newm > 0.f;                      // rem now = ACTIVE flag
    __syncthreads();
    // fused compaction + new degree + D (warp per row, 32 rows per warp)
    int wid = i >> 5, lane = i & 31;
    #pragma unroll 1
    for (int rr = 0; rr < 32; ++rr) {
        int rloc = wid * 32 + rr;
        int row  = b * Nn + rloc;
        int deg  = g_deg[row];
        int* adj = g_adj + (size_t)row * MAXDEG;
        int wcnt = 0;
        for (int c = 0; c < deg; c += 32) {
            int idx = c + lane;
            int j = (idx < deg) ? adj[idx] : 0;
            bool act = (idx < deg) && rem[j];
            unsigned bal = __ballot_sync(0xffffffffu, act);
            if (act) adj[wcnt + __popc(bal & ((1u << lane) - 1u))] = j;
            wcnt += __popc(bal);
        }
        if (lane == 0) {
            g_deg[row] = wcnt;
            float mr = rem[rloc] ? 1.0f : 0.0f;
            float rowsum = mr * (float)wcnt + 1.0f;
            g_D[row] = 1.0f / sqrtf(rowsum + EPSf);
        }
    }
}

// ---------------- 5) tiny final FC from g_xmax ----------------------------
__global__ void final_fc(const float* __restrict__ Wfc,
                         const float* __restrict__ bfc,
                         float* __restrict__ out) {
    __shared__ float gm[Ff];
    int b = blockIdx.x;
    if (threadIdx.x < Ff) gm[threadIdx.x] = g_xmax[b * Ff + threadIdx.x];
    __syncthreads();
    if (threadIdx.x < OUTD) {
        float acc = bfc[threadIdx.x];
        #pragma unroll
        for (int ff = 0; ff < Ff; ++ff)
            acc = fmaf(gm[ff], Wfc[ff * OUTD + threadIdx.x], acc);
        out[b * OUTD + threadIdx.x] = acc;
    }
}

// ---------------- launch ---------------------------------------------------
extern "C" void kernel_launch(void* const* d_in, const int* in_sizes, int n_in,
                              void* d_out, int out_size) {
    const float* x    = (const float*)d_in[0];
    const float* A    = (const float*)d_in[1];
    const float* mask = (const float*)d_in[2];
    const int*   nn   = (const int*)  d_in[3];
    const float* W0   = (const float*)d_in[4];
    const float* b0   = (const float*)d_in[5];
    const float* W1   = (const float*)d_in[6];
    const float* b1   = (const float*)d_in[7];
    const float* W2   = (const float*)d_in[8];
    const float* b2   = (const float*)d_in[9];
    const float* p0   = (const float*)d_in[10];
    const float* p1   = (const float*)d_in[11];
    const float* Wfc  = (const float*)d_in[12];
    const float* bfc  = (const float*)d_in[13];
    float* out = (float*)d_out;

    const int SGRID = (Bz * Nn) / 8;    // warp-per-node kernels
    const int GGRID = (Bz * Nn) / 32;   // gemm: 8 warps/block, 4 rows/warp

    // layer 0 (adjacency build fused with GEMM)
    layer0_fused<<<GGRID, 256>>>(x, A, mask, nn, W0);
    spmm_relu<<<SGRID, 256>>>(b0, p0);
    pool_apply<<<Bz, Nn>>>(0);          // sort + compaction + D fused

    // layer 1
    gemm_fused<<<GGRID, 256>>>(W1);
    spmm_relu<<<SGRID, 256>>>(b1, p1);
    pool_apply<<<Bz, Nn>>>(1);          // sort + compaction + D fused

    // layer 2 (gconv fused with global max pool)
    gemm_fused<<<GGRID, 256>>>(W2);
    spmm_max<<<SGRID, 256>>>(b2);

    final_fc<<<Bz, 64>>>(Wfc, bfc, out);
}

// round 17
// speedup vs baseline: 1.2572x; 1.2572x over previous
#include <cuda_runtime.h>
#include <cuda_fp16.h>
#include <math.h>

#define Bz   32
#define Nn   1024
#define CIN  128
#define Ff   64
#define OUTD 10
#define MAXDEG 96
#define EPSf 1e-5f

typedef unsigned long long ull;

// ---------------- scratch (device globals; no allocation) ----------------
__device__ int     g_adj[Bz * Nn * MAXDEG]; // adjacency lists (compacted per layer)
__device__ int     g_deg[Bz * Nn];
__device__ float   g_x[Bz * Nn * Ff];       // gconv output (layers 0,1)
__device__ __half2 g_uwh[Bz * Nn * 32];     // fp16 D*m*u  (gathered by spmm)
__device__ float   g_ud[Bz * Nn * Ff];      // D*D*u  (diag term, fp32)
__device__ float   g_D[Bz * Nn];
__device__ float   g_mask[Bz * Nn];
__device__ unsigned char g_mask8[Bz * Nn];  // byte mask for dense gathers
__device__ float   g_sc[Bz * Nn];           // tanh(y)*new_mask
__device__ int     g_nnodes[Bz * 3];
__device__ float   g_y[Bz * Nn];
__device__ float   g_xmax[Bz * Ff];         // layer-2 global max (atomicMax target)

// ------ 1) fused: adjacency extraction + layer-0 GEMM + D + uw/ud --------
__global__ void layer0_fused(const float* __restrict__ x,
                             const float* __restrict__ A,
                             const float* __restrict__ mask,
                             const int*   __restrict__ nn,
                             const float* __restrict__ W) {
    __shared__ float2 Ws[CIN * 32];
    const float2* W2 = (const float2*)W;
    for (int i = threadIdx.x; i < CIN * 32; i += 256) Ws[i] = W2[i];
    if (blockIdx.x == 0 && threadIdx.x < Bz) g_nnodes[threadIdx.x] = nn[threadIdx.x];
    int wid = threadIdx.x >> 5, lane = threadIdx.x & 31;
    int row0 = blockIdx.x * 32 + wid * 4;
    float2 xa[4], xb[4];
    #pragma unroll
    for (int r = 0; r < 4; ++r) {
        const float2* xr = (const float2*)(x + (size_t)(row0 + r) * CIN);
        xa[r] = __ldcs(xr + lane);
        xb[r] = __ldcs(xr + lane + 32);
    }
    int   deg[4]; float mrow[4];
    #pragma unroll
    for (int r = 0; r < 4; ++r) {
        int row = row0 + r;
        const float4* Arow4 = (const float4*)(A + (size_t)row * Nn);
        int* adj = g_adj + (size_t)row * MAXDEG;
        int cnt = 0;
        #pragma unroll
        for (int half = 0; half < 2; ++half) {
            float4 va[4];
            #pragma unroll
            for (int it = 0; it < 4; ++it)                       // MLP=4, streaming
                va[it] = __ldcs(Arow4 + (half * 4 + it) * 32 + lane);
            #pragma unroll
            for (int it = 0; it < 4; ++it) {
                int jb = (half * 4 + it) * 128 + lane * 4;
                #pragma unroll
                for (int s = 0; s < 4; ++s) {
                    float vs = (s == 0) ? va[it].x : (s == 1) ? va[it].y
                             : (s == 2) ? va[it].z : va[it].w;
                    unsigned bal = __ballot_sync(0xffffffffu, vs != 0.0f);
                    if (vs != 0.0f) {
                        int pos = cnt + __popc(bal & ((1u << lane) - 1u));
                        if (pos < MAXDEG) adj[pos] = jb + s;
                    }
                    cnt += __popc(bal);
                }
            }
        }
        deg[r]  = min(cnt, MAXDEG);
        mrow[r] = mask[row];
        if (lane == 0) {
            g_deg[row]   = deg[r];
            g_mask[row]  = mrow[r];
            g_mask8[row] = mrow[r] > 0.f;
        }
    }
    __syncthreads();
    float acc[4][2] = {};
    #pragma unroll
    for (int k2 = 0; k2 < 32; ++k2) {
        float2 wv0 = Ws[(2 * k2)     * 32 + lane];
        float2 wv1 = Ws[(2 * k2 + 1) * 32 + lane];
        #pragma unroll
        for (int r = 0; r < 4; ++r) {
            float u = __shfl_sync(0xffffffffu, xa[r].x, k2);
            float v = __shfl_sync(0xffffffffu, xa[r].y, k2);
            acc[r][0] = fmaf(u, wv0.x, fmaf(v, wv1.x, acc[r][0]));
            acc[r][1] = fmaf(u, wv0.y, fmaf(v, wv1.y, acc[r][1]));
        }
    }
    #pragma unroll
    for (int k2 = 0; k2 < 32; ++k2) {
        float2 wv0 = Ws[(64 + 2 * k2) * 32 + lane];
        float2 wv1 = Ws[(65 + 2 * k2) * 32 + lane];
        #pragma unroll
        for (int r = 0; r < 4; ++r) {
            float u = __shfl_sync(0xffffffffu, xb[r].x, k2);
            float v = __shfl_sync(0xffffffffu, xb[r].y, k2);
            acc[r][0] = fmaf(u, wv0.x, fmaf(v, wv1.x, acc[r][0]));
            acc[r][1] = fmaf(u, wv0.y, fmaf(v, wv1.y, acc[r][1]));
        }
    }
    #pragma unroll
    for (int r = 0; r < 4; ++r) {
        int row = row0 + r;
        float rowsum = mrow[r] * (float)deg[r] + 1.0f;   // +1: identity in A_hat
        float D = 1.0f / sqrtf(rowsum + EPSf);
        if (lane == 0) g_D[row] = D;
        float Dm = D * mrow[r], DD = D * D;
        g_uwh[(size_t)row * 32 + lane] = __floats2half2_rn(Dm * acc[r][0], Dm * acc[r][1]);
        ((float2*)g_ud)[(size_t)row * 32 + lane] = make_float2(DD * acc[r][0], DD * acc[r][1]);
    }
}

// ---- 1b) compaction + D: graph mask staged to shared ---------------------
__global__ void compact_D() {
    __shared__ unsigned char Ms[Nn];
    int wid  = threadIdx.x >> 5, lane = threadIdx.x & 31;
    int row  = blockIdx.x * 8 + wid;          // 8 rows/block, same graph
    int base = row & ~(Nn - 1);
    ((uchar4*)Ms)[threadIdx.x] = ((const uchar4*)(g_mask8 + base))[threadIdx.x];
    __syncthreads();
    float m  = g_mask[row];
    int  deg = g_deg[row];
    int* adj = g_adj + (size_t)row * MAXDEG;
    int wcnt = 0;
    for (int c = 0; c < deg; c += 32) {
        int idx = c + lane;
        int j = (idx < deg) ? adj[idx] : 0;
        bool act = (idx < deg) && Ms[j];
        unsigned bal = __ballot_sync(0xffffffffu, act);
        if (act) adj[wcnt + __popc(bal & ((1u << lane) - 1u))] = j;
        wcnt += __popc(bal);
    }
    if (lane == 0) {
        g_deg[row] = wcnt;
        float rowsum = m * (float)wcnt + 1.0f;
        g_D[row] = 1.0f / sqrtf(rowsum + EPSf);
    }
}

// ------- 2) pure GEMM: u = sc*(X@W); 8 rows/warp (one Ws read -> 32 FMA) --
__global__ void gemm_fused(const float* __restrict__ W) {
    __shared__ float2 Ws[Ff * 32];
    const float2* W2 = (const float2*)W;
    for (int i = threadIdx.x; i < Ff * 32; i += 256) Ws[i] = W2[i];
    int wid = threadIdx.x >> 5, lane = threadIdx.x & 31;
    int row0 = blockIdx.x * 64 + wid * 8;
    float2 xa[8];
    #pragma unroll
    for (int r = 0; r < 8; ++r)
        xa[r] = ((const float2*)g_x)[(size_t)(row0 + r) * 32 + lane];
    __syncthreads();
    float acc[8][2] = {};
    #pragma unroll
    for (int k2 = 0; k2 < 32; ++k2) {
        float2 wv0 = Ws[(2 * k2)     * 32 + lane];
        float2 wv1 = Ws[(2 * k2 + 1) * 32 + lane];
        #pragma unroll
        for (int r = 0; r < 8; ++r) {
            float u = __shfl_sync(0xffffffffu, xa[r].x, k2);
            float v = __shfl_sync(0xffffffffu, xa[r].y, k2);
            acc[r][0] = fmaf(u, wv0.x, fmaf(v, wv1.x, acc[r][0]));
            acc[r][1] = fmaf(u, wv0.y, fmaf(v, wv1.y, acc[r][1]));
        }
    }
    #pragma unroll
    for (int r = 0; r < 8; ++r) {
        int row = row0 + r;
        float D = g_D[row];
        float m = g_mask[row];
        float s = g_sc[row];                  // pooling rescale: (sc*x)@W == sc*(x@W)
        float a0 = acc[r][0] * s, a1 = acc[r][1] * s;
        float Dm = D * m, DD = D * D;
        g_uwh[(size_t)row * 32 + lane] = __floats2half2_rn(Dm * a0, Dm * a1);
        ((float2*)g_ud)[(size_t)row * 32 + lane] = make_float2(DD * a0, DD * a1);
    }
}

// -------------- shared gather body: fp16 gathers, fp32 accumulate ---------
__device__ __forceinline__ float2 spmm_body(int node, int lane,
                                            const float* __restrict__ bias) {
    int base = node & ~(Nn - 1);
    float D = g_D[node];
    float2 ud = ((const float2*)g_ud)[(size_t)node * 32 + lane];
    float2 bv = ((const float2*)bias)[lane];
    float s0 = 0.f, s1 = 0.f;
    if (g_mask[node] > 0.f) {
        const int* adj = g_adj + (size_t)node * MAXDEG;
        int deg = g_deg[node];
        const __half2* uwb = g_uwh + (size_t)base * 32 + lane;
        int t = 0;
        for (; t + 4 <= deg; t += 4) {
            int4 jv = *(const int4*)(adj + t);
            __half2 v0 = uwb[jv.x * 32];
            __half2 v1 = uwb[jv.y * 32];
            __half2 v2 = uwb[jv.z * 32];
            __half2 v3 = uwb[jv.w * 32];
            __half2 h = __hadd2(__hadd2(v0, v1), __hadd2(v2, v3));
            float2 f = __half22float2(h);
            s0 += f.x; s1 += f.y;
        }
        for (; t < deg; ++t) {
            float2 f = __half22float2(uwb[adj[t] * 32]);
            s0 += f.x; s1 += f.y;
        }
    }
    float x0 = fmaxf(fmaf(D, s0, ud.x + bv.x), 0.f);
    float x1 = fmaxf(fmaf(D, s1, ud.y + bv.y), 0.f);
    return make_float2(x0, x1);
}

// -------- 3) layers 0/1: x = gconv, + fused pooling score -----------------
__global__ void spmm_relu(const float* __restrict__ bias,
                          const float* __restrict__ p) {
    int node = (blockIdx.x * blockDim.x + threadIdx.x) >> 5;
    int lane = threadIdx.x & 31;
    float2 xv = spmm_body(node, lane, bias);
    ((float2*)g_x)[(size_t)node * 32 + lane] = xv;
    float2 pv = ((const float2*)p)[lane];
    float d = xv.x * pv.x + xv.y * pv.y;
    float n = pv.x * pv.x + pv.y * pv.y;
    #pragma unroll
    for (int o = 16; o; o >>= 1) {
        d += __shfl_xor_sync(0xffffffffu, d, o);
        n += __shfl_xor_sync(0xffffffffu, n, o);
    }
    if (lane == 0) g_y[node] = d / sqrtf(n);
}

// -------- 3b) layer 2: gconv fused with global max (no g_x write) ---------
__global__ void spmm_max(const float* __restrict__ bias) {
    __shared__ float2 pm[8][32];
    int node = (blockIdx.x * blockDim.x + threadIdx.x) >> 5;
    int wid  = threadIdx.x >> 5;
    int lane = threadIdx.x & 31;
    float2 xv = spmm_body(node, lane, bias);
    pm[wid][lane] = xv;
    __syncthreads();
    if (wid == 0) {
        float2 mx = pm[0][lane];
        #pragma unroll
        for (int w = 1; w < 8; ++w) {
            float2 v = pm[w][lane];
            mx.x = fmaxf(mx.x, v.x);
            mx.y = fmaxf(mx.y, v.y);
        }
        int b = node >> 10;
        unsigned* gx = (unsigned*)g_xmax + b * Ff + 2 * lane;
        atomicMax(gx,     __float_as_uint(mx.x));   // x >= 0: bits monotone
        atomicMax(gx + 1, __float_as_uint(mx.y));
    }
}

// -------- 4) pooling via hybrid register/shared bitonic sort --------------
__device__ __forceinline__ ull bsw(ull v, int i, int j, int k) {
    ull vp = __shfl_xor_sync(0xffffffffu, v, j);
    bool keepmin = ((i & j) == 0) == ((i & k) == 0);
    ull mn = v < vp ? v : vp;
    ull mx = v < vp ? vp : v;
    return keepmin ? mn : mx;
}

__global__ void pool_apply(int step) {
    __shared__ ull sk[Nn];
    __shared__ unsigned char rem[Nn];
    int b = blockIdx.x;
    int i = threadIdx.x;
    int node = b * Nn + i;
    float m = g_mask[node];
    float y = g_y[node];
    float ye = (m > 0.f) ? y : INFINITY;      // invalid nodes sort last
    unsigned int bits = __float_as_uint(ye);
    unsigned int mono = (bits & 0x80000000u) ? ~bits : (bits | 0x80000000u);
    ull v = ((ull)mono << 10) | (unsigned int)i;
    rem[i] = 0;
    if (step == 1 && i < Ff) g_xmax[b * Ff + i] = 0.f;   // reset for spmm_max
    int n  = g_nnodes[step * Bz + b];
    int nr = (int)((float)n * 0.2f);          // bit-matches f32 arithmetic
    if (i == 0) g_nnodes[(step + 1) * Bz + b] = n - nr;
    #pragma unroll
    for (int k = 2; k <= 32; k <<= 1)
        #pragma unroll
        for (int j = k >> 1; j > 0; j >>= 1) v = bsw(v, i, j, k);
    #pragma unroll 1
    for (int k = 64; k <= Nn; k <<= 1) {
        #pragma unroll 1
        for (int j = k >> 1; j >= 32; j >>= 1) {
            sk[i] = v;
            __syncthreads();
            ull vp = sk[i ^ j];
            bool keepmin = ((i & j) == 0) == ((i & k) == 0);
            v = keepmin ? (v < vp ? v : vp) : (v < vp ? vp : v);
            __syncthreads();
        }
        #pragma unroll
        for (int j = 16; j > 0; j >>= 1) v = bsw(v, i, j, k);
    }
    if (i < nr) rem[(int)(v & 1023u)] = 1;    // lowest-nr ranks removed
    __syncthreads();
    float newm = (m > 0.f && !rem[i]) ? 1.f : 0.f;
    g_mask[node]  = newm;
    g_mask8[node] = newm > 0.f;
    g_sc[node]    = tanhf(y) * newm;          // consumed by next gemm
}

// ---------------- 5) tiny final FC from g_xmax ----------------------------
__global__ void final_fc(const float* __restrict__ Wfc,
                         const float* __restrict__ bfc,
                         float* __restrict__ out) {
    __shared__ float gm[Ff];
    int b = blockIdx.x;
    if (threadIdx.x < Ff) gm[threadIdx.x] = g_xmax[b * Ff + threadIdx.x];
    __syncthreads();
    if (threadIdx.x < OUTD) {
        float acc = bfc[threadIdx.x];
        #pragma unroll
        for (int ff = 0; ff < Ff; ++ff)
            acc = fmaf(gm[ff], Wfc[ff * OUTD + threadIdx.x], acc);
        out[b * OUTD + threadIdx.x] = acc;
    }
}

// ---------------- launch ---------------------------------------------------
extern "C" void kernel_launch(void* const* d_in, const int* in_sizes, int n_in,
                              void* d_out, int out_size) {
    const float* x    = (const float*)d_in[0];
    const float* A    = (const float*)d_in[1];
    const float* mask = (const float*)d_in[2];
    const int*   nn   = (const int*)  d_in[3];
    const float* W0   = (const float*)d_in[4];
    const float* b0   = (const float*)d_in[5];
    const float* W1   = (const float*)d_in[6];
    const float* b1   = (const float*)d_in[7];
    const float* W2   = (const float*)d_in[8];
    const float* b2   = (const float*)d_in[9];
    const float* p0   = (const float*)d_in[10];
    const float* p1   = (const float*)d_in[11];
    const float* Wfc  = (const float*)d_in[12];
    const float* bfc  = (const float*)d_in[13];
    float* out = (float*)d_out;

    const int SGRID = (Bz * Nn) / 8;    // warp-per-node kernels
    const int L0GRID = (Bz * Nn) / 32;  // layer0: 8 warps/block, 4 rows/warp
    const int GGRID  = (Bz * Nn) / 64;  // gemm:   8 warps/block, 8 rows/warp

    // layer 0 (adjacency build fused with GEMM)
    layer0_fused<<<L0GRID, 256>>>(x, A, mask, nn, W0);
    spmm_relu<<<SGRID, 256>>>(b0, p0);
    pool_apply<<<Bz, Nn>>>(0);

    // layer 1
    compact_D<<<SGRID, 256>>>();
    gemm_fused<<<GGRID, 256>>>(W1);
    spmm_relu<<<SGRID, 256>>>(b1, p1);
    pool_apply<<<Bz, Nn>>>(1);

    // layer 2 (gconv fused with global max pool)
    compact_D<<<SGRID, 256>>>();
    gemm_fused<<<GGRID, 256>>>(W2);
    spmm_max<<<SGRID, 256>>>(b2);

    final_fc<<<Bz, 64>>>(Wfc, bfc, out);
}